// round 6
// baseline (speedup 1.0000x reference)
#include <cuda_runtime.h>

// MatrixMemory fused (R6): 32B-contiguous per-lane accesses (LDG/STG.256 fusable).
//   y = state @ query (per-batch GEMV), dM = d_out ⊗ key (per-batch outer)
// Each lane owns 8 consecutive floats of a row (two ADJACENT float4 at a
// 32B-aligned base -> ptxas can fuse to 256-bit ops). Warp = 4 rows,
// 16384 blocks x 256 threads, no smem/barriers.

#define B_  2048
#define DK_ 256
#define DV_ 256

__global__ __launch_bounds__(256, 8)
void mm_fused6_kernel(const float4* __restrict__ state,   // [B, DV, DK] as float4
                      const float4* __restrict__ query,   // [B, DK] as float4
                      const float4* __restrict__ keyv,    // [B, DK] as float4
                      const float*  __restrict__ dout,    // [B, DV]
                      float4*       __restrict__ y,       // [B, DV] as float4
                      float4*       __restrict__ dM)      // [B, DV, DK] as float4
{
    const int b  = blockIdx.x >> 3;            // 8 blocks per batch
    const int rb = (blockIdx.x & 7) << 5;      // 32 v-rows per block

    const int tid  = threadIdx.x;
    const int w    = tid >> 5;
    const int lane = tid & 31;
    const long row0 = (long)b * DV_ + rb + w * 4;   // 4 rows per warp

    // lane owns floats [lane*8 .. lane*8+7] of each row: float4 index lane*2, lane*2+1
    const int li = lane * 2;
    const float4* p = state + row0 * (DK_ / 4) + li;

    // ---- front-batch loads: 4 rows x 32B (adjacent float4 pairs) ----
    float4 a[8];
    #pragma unroll
    for (int j = 0; j < 4; j++) {
        a[2*j]   = __ldcs(p + j * 64);
        a[2*j+1] = __ldcs(p + j * 64 + 1);
    }

    // vectors: 1KB per batch, L2-resident (reused by 8 blocks)
    const float4 q0 = __ldg(query + b * 64 + li);
    const float4 q1 = __ldg(query + b * 64 + li + 1);
    const float4 k0 = __ldg(keyv  + b * 64 + li);
    const float4 k1 = __ldg(keyv  + b * 64 + li + 1);

    float dv[4];
    #pragma unroll
    for (int j = 0; j < 4; j++) dv[j] = __ldg(dout + row0 + j);

    float4* pd = dM + row0 * (DK_ / 4) + li;
    float yv[4];

    #pragma unroll
    for (int j = 0; j < 4; j++) {
        // outer-product row write: adjacent 16B pair (fusable to STG.256)
        const float d = dv[j];
        float4 o0 = make_float4(d * k0.x, d * k0.y, d * k0.z, d * k0.w);
        float4 o1 = make_float4(d * k1.x, d * k1.y, d * k1.z, d * k1.w);
        __stcs(pd + j * 64,     o0);
        __stcs(pd + j * 64 + 1, o1);

        // dot-product partial + warp reduce
        float s = a[2*j].x   * q0.x + a[2*j].y   * q0.y
                + a[2*j].z   * q0.z + a[2*j].w   * q0.w
                + a[2*j+1].x * q1.x + a[2*j+1].y * q1.y
                + a[2*j+1].z * q1.z + a[2*j+1].w * q1.w;
        #pragma unroll
        for (int off = 16; off > 0; off >>= 1)
            s += __shfl_xor_sync(0xFFFFFFFFu, s, off);
        yv[j] = s;                                  // valid in lane 0
    }

    // one aligned 16B y-store per warp (rows row0..row0+3)
    if (lane == 0)
        y[row0 >> 2] = make_float4(yv[0], yv[1], yv[2], yv[3]);
}

extern "C" void kernel_launch(void* const* d_in, const int* in_sizes, int n_in,
                              void* d_out, int out_size)
{
    const float4* state = (const float4*)d_in[0];
    const float4* query = (const float4*)d_in[1];
    const float4* keyv  = (const float4*)d_in[2];
    const float*  dov   = (const float*) d_in[3];

    float* out = (float*)d_out;
    float4* y  = (float4*)out;                     // [B, DV]
    float4* dM = (float4*)(out + (long)B_ * DV_);  // [B, DV, DK]

    dim3 grid(B_ * 8);   // 8 blocks/batch, 8 warps, 4 rows/warp
    dim3 block(256);
    mm_fused6_kernel<<<grid, block>>>(state, query, keyv, dov, y, dM);
}

// round 7
// speedup vs baseline: 1.3800x; 1.3800x over previous
#include <cuda_runtime.h>

// MatrixMemory (R7): direction-specialized CTAs, interleaved even/odd.
//   even blocks: dM[b][v][:] = d_out[b][v] * key[b][:]   (pure write stream)
//   odd  blocks: y[b][v] = dot(state[b][v][:], query[b][:]) (pure read stream)
// Both directions concurrent chip-wide; each warp's stream is single-direction
// for max per-direction MLP. Lane-contiguous 16B accesses (R6 lesson).

#define B_  2048
#define DK_ 256
#define DV_ 256

__global__ __launch_bounds__(256, 8)
void mm_split7_kernel(const float4* __restrict__ state,   // [B, DV, DK] as float4
                      const float4* __restrict__ query,   // [B, DK] as float4
                      const float4* __restrict__ keyv,    // [B, DK] as float4
                      const float*  __restrict__ dout,    // [B, DV]
                      float4*       __restrict__ y,       // [B, DV] as float4
                      float4*       __restrict__ dM)      // [B, DV, DK] as float4
{
    const int t  = blockIdx.x >> 1;            // tile id 0..16383
    const int b  = t >> 3;                     // 8 tiles per batch
    const int rb = (t & 7) << 5;               // 32 v-rows per tile

    const int tid  = threadIdx.x;
    const int w    = tid >> 5;
    const int lane = tid & 31;
    const long row0 = (long)b * DV_ + rb + w * 4;   // 4 rows per warp

    if (blockIdx.x & 1) {
        // ---------------- READ stream: y = state @ query ----------------
        const float4* p = state + row0 * (DK_ / 4);

        float4 a[8];
        #pragma unroll
        for (int j = 0; j < 4; j++) {
            a[2*j]   = __ldcs(p + j * 64 + lane);
            a[2*j+1] = __ldcs(p + j * 64 + 32 + lane);
        }

        const float4 q0 = __ldg(query + b * 64 + lane);
        const float4 q1 = __ldg(query + b * 64 + 32 + lane);

        float yv[4];
        #pragma unroll
        for (int j = 0; j < 4; j++) {
            float s = a[2*j].x   * q0.x + a[2*j].y   * q0.y
                    + a[2*j].z   * q0.z + a[2*j].w   * q0.w
                    + a[2*j+1].x * q1.x + a[2*j+1].y * q1.y
                    + a[2*j+1].z * q1.z + a[2*j+1].w * q1.w;
            #pragma unroll
            for (int off = 16; off > 0; off >>= 1)
                s += __shfl_xor_sync(0xFFFFFFFFu, s, off);
            yv[j] = s;
        }
        if (lane == 0)
            y[row0 >> 2] = make_float4(yv[0], yv[1], yv[2], yv[3]);
    } else {
        // ---------------- WRITE stream: dM = d_out ⊗ key ----------------
        const float4 k0 = __ldg(keyv + b * 64 + lane);
        const float4 k1 = __ldg(keyv + b * 64 + 32 + lane);

        float dv[4];
        #pragma unroll
        for (int j = 0; j < 4; j++) dv[j] = __ldg(dout + row0 + j);

        float4* pd = dM + row0 * (DK_ / 4);
        #pragma unroll
        for (int j = 0; j < 4; j++) {
            const float d = dv[j];
            float4 o0 = make_float4(d * k0.x, d * k0.y, d * k0.z, d * k0.w);
            float4 o1 = make_float4(d * k1.x, d * k1.y, d * k1.z, d * k1.w);
            __stcs(pd + j * 64 + lane,      o0);
            __stcs(pd + j * 64 + 32 + lane, o1);
        }
    }
}

extern "C" void kernel_launch(void* const* d_in, const int* in_sizes, int n_in,
                              void* d_out, int out_size)
{
    const float4* state = (const float4*)d_in[0];
    const float4* query = (const float4*)d_in[1];
    const float4* keyv  = (const float4*)d_in[2];
    const float*  dov   = (const float*) d_in[3];

    float* out = (float*)d_out;
    float4* y  = (float4*)out;                     // [B, DV]
    float4* dM = (float4*)(out + (long)B_ * DV_);  // [B, DV, DK]

    dim3 grid(B_ * 8 * 2);  // even = write tile, odd = read tile (interleaved)
    dim3 block(256);
    mm_split7_kernel<<<grid, block>>>(state, query, keyv, dov, y, dM);
}